// round 10
// baseline (speedup 1.0000x reference)
#include <cuda_runtime.h>
#include <cuda_fp16.h>
#include <math.h>

// Problem constants (fixed by the reference)
#define NNODES 100000
#define NEDGES 3200000
#define FIN    11
#define HDIM   32
#define CDIM   16
#define CAP    96      // padded CSR slots per node; deg ~ Poisson(32), P(>=96) ~ e^-41
#define CAP4   24      // CAP in int4 units
#define NBIN   96

#define GE4 3125       // edge blocks, 4 edges/thread (3.2M / 4 / 256, exact)
#define GW  12500      // node-warp blocks for mm1 (100000 / 8, exact)
#define GQ  3125       // 4-nodes-per-warp blocks (25000 warps, exact)
#define GO  1563       // 8-nodes-per-warp blocks for l4 (12500 warps, guarded)
#define GN  391        // node blocks (100000 / 256, guarded)

// ---------------- scratch (static __device__ — no allocation allowed) -------
__device__ int    g_cnt[NNODES];                       // in-degree / fill cursor
__device__ float  g_dinv[NNODES];
__device__ int    g_hist[NBIN];                        // degree histogram
__device__ int    g_cursor[NBIN];                      // bin placement cursors
__device__ int    g_perm[NNODES];                      // degree-sorted node order
__device__ __align__(16) int    g_csr[NNODES * CAP];   // padded rows, src only
__device__ __align__(16) __half g_h1[NNODES * HDIM];   // after prep: h1 * dinv
__device__ __align__(16) __half g_h2[NNODES * HDIM];   // h2 * dinv
__device__ __align__(16) __half g_h3[NNODES * CDIM];   // h3 * dinv

// ---------------- fused: CSR fill (blocks [0,GE4)) ∥ mm1 (rest) -------------
__global__ void k_build(const int4* __restrict__ src4, const int4* __restrict__ dst4,
                        const float* __restrict__ x, const float* __restrict__ W1) {
    __shared__ float sW[FIN * HDIM];
    if (blockIdx.x < GE4) {
        int e = blockIdx.x * blockDim.x + threadIdx.x;
        int4 d = dst4[e];
        int4 s = src4[e];
        g_csr[d.x * CAP + atomicAdd(&g_cnt[d.x], 1)] = s.x;
        g_csr[d.y * CAP + atomicAdd(&g_cnt[d.y], 1)] = s.y;
        g_csr[d.z * CAP + atomicAdd(&g_cnt[d.z], 1)] = s.z;
        g_csr[d.w * CAP + atomicAdd(&g_cnt[d.w], 1)] = s.w;
    } else {
        int t = threadIdx.x;
        for (int i = t; i < FIN * HDIM; i += blockDim.x) sW[i] = W1[i];
        __syncthreads();
        int gw = ((blockIdx.x - GE4) * blockDim.x + t) >> 5;
        int l  = t & 31;
        float xv = (l < FIN) ? x[gw * FIN + l] : 0.0f;
        float acc = 0.0f;
        #pragma unroll
        for (int k = 0; k < FIN; k++)
            acc += __shfl_sync(0xFFFFFFFFu, xv, k) * sW[k * HDIM + l];
        g_h1[gw * HDIM + l] = __float2half(acc);
    }
}

// ---------------- prep: dinv + scale h1 in place + degree histogram ---------
// thread per node; row scaling via 4x uint4 (coalesced across the warp)
__global__ void k_prep() {
    __shared__ int sh[NBIN];
    int t = threadIdx.x;
    if (t < NBIN) sh[t] = 0;
    __syncthreads();
    int n = blockIdx.x * blockDim.x + t;
    if (n < NNODES) {
        int deg = g_cnt[n];
        float di = rsqrtf((float)deg + 1.0f);
        g_dinv[n] = di;
        atomicAdd(&sh[min(deg, NBIN - 1)], 1);
        __half2 d2 = __float2half2_rn(di);
        uint4* row = (uint4*)(g_h1 + n * HDIM);
        #pragma unroll
        for (int i = 0; i < 4; i++) {
            uint4 v = row[i];
            __half2* p = (__half2*)&v;
            p[0] = __hmul2(p[0], d2);
            p[1] = __hmul2(p[1], d2);
            p[2] = __hmul2(p[2], d2);
            p[3] = __hmul2(p[3], d2);
            row[i] = v;
        }
    }
    __syncthreads();
    if (t < NBIN && sh[t]) atomicAdd(&g_hist[t], sh[t]);
}

// ---------------- exclusive scan over 96 bins -> g_cursor --------------------
__global__ void k_binscan() {
    __shared__ int s[128];
    int t = threadIdx.x;                       // 128 threads
    int mine = (t < NBIN) ? g_hist[t] : 0;
    s[t] = mine;
    __syncthreads();
    #pragma unroll
    for (int off = 1; off < 128; off <<= 1) {
        int v = (t >= off) ? s[t - off] : 0;
        __syncthreads();
        s[t] += v;
        __syncthreads();
    }
    if (t < NBIN) g_cursor[t] = s[t] - mine;   // exclusive prefix
}

// ---------------- placement: g_perm = nodes grouped by degree ----------------
__global__ void k_place() {
    __shared__ int sh[NBIN];
    __shared__ int sbase[NBIN];
    int t = threadIdx.x;
    if (t < NBIN) sh[t] = 0;
    __syncthreads();
    int n = blockIdx.x * blockDim.x + t;
    int bin = 0, loc = 0;
    bool valid = n < NNODES;
    if (valid) {
        bin = min(g_cnt[n], NBIN - 1);
        loc = atomicAdd(&sh[bin], 1);
    }
    __syncthreads();
    if (t < NBIN && sh[t] > 0) sbase[t] = atomicAdd(&g_cursor[t], sh[t]);
    __syncthreads();
    if (valid) g_perm[sbase[bin] + loc] = n;
}

// ---- double-buffered gather macro body: fp16 accumulate, 8B/lane rows ------
// Accumulates into __half2 acc0/acc1 from table h (uint2 rows of 8 per node
// for STRIDE=8, or 4 for STRIDE=4). qr ends holding the remainder chunk.
#define GATHER_ROW(h, STRIDE)                                                 \
    const int4* row = (const int4*)&g_csr[n * CAP];                           \
    int deg = g_cnt[n];                                                       \
    int nIt = deg >> 2, rem = deg & 3;                                        \
    int4 qc = row[0];                                                         \
    int4 qn = row[1];                                                         \
    uint2 A0, A1, A2, A3;                                                     \
    if (nIt > 0) {                                                            \
        A0 = h[qc.x * STRIDE + l]; A1 = h[qc.y * STRIDE + l];                 \
        A2 = h[qc.z * STRIDE + l]; A3 = h[qc.w * STRIDE + l];                 \
    }                                                                         \
    for (int j = 1; j < nIt; j++) {                                           \
        int4 q3 = row[j + 1];                                                 \
        uint2 B0 = h[qn.x * STRIDE + l], B1 = h[qn.y * STRIDE + l];           \
        uint2 B2 = h[qn.z * STRIDE + l], B3 = h[qn.w * STRIDE + l];           \
        __half2 t0 = __hadd2(*(__half2*)&A0.x, *(__half2*)&A1.x);             \
        __half2 t1 = __hadd2(*(__half2*)&A2.x, *(__half2*)&A3.x);             \
        acc0 = __hadd2(acc0, __hadd2(t0, t1));                                \
        __half2 u0 = __hadd2(*(__half2*)&A0.y, *(__half2*)&A1.y);             \
        __half2 u1 = __hadd2(*(__half2*)&A2.y, *(__half2*)&A3.y);             \
        acc1 = __hadd2(acc1, __hadd2(u0, u1));                                \
        A0 = B0; A1 = B1; A2 = B2; A3 = B3;                                   \
        qn = q3;                                                              \
    }                                                                         \
    if (nIt > 0) {                                                            \
        __half2 t0 = __hadd2(*(__half2*)&A0.x, *(__half2*)&A1.x);             \
        __half2 t1 = __hadd2(*(__half2*)&A2.x, *(__half2*)&A3.x);             \
        acc0 = __hadd2(acc0, __hadd2(t0, t1));                                \
        __half2 u0 = __hadd2(*(__half2*)&A0.y, *(__half2*)&A1.y);             \
        __half2 u1 = __hadd2(*(__half2*)&A2.y, *(__half2*)&A3.y);             \
        acc1 = __hadd2(acc1, __hadd2(u0, u1));                                \
    }                                                                         \
    int4 qr = (nIt > 0) ? qn : qc;                                            \
    if (rem > 0) {                                                            \
        uint2 v = h[qr.x * STRIDE + l];                                       \
        acc0 = __hadd2(acc0, *(__half2*)&v.x);                                \
        acc1 = __hadd2(acc1, *(__half2*)&v.y);                                \
    }                                                                         \
    if (rem > 1) {                                                            \
        uint2 v = h[qr.y * STRIDE + l];                                       \
        acc0 = __hadd2(acc0, *(__half2*)&v.x);                                \
        acc1 = __hadd2(acc1, *(__half2*)&v.y);                                \
    }                                                                         \
    if (rem > 2) {                                                            \
        uint2 v = h[qr.z * STRIDE + l];                                       \
        acc0 = __hadd2(acc0, *(__half2*)&v.x);                                \
        acc1 = __hadd2(acc1, *(__half2*)&v.y);                                \
    }

// ---------------- layer 2: gather(h1') + ReLU + GEMM(W2) -> h2' (fp16) ------
// 4 nodes/warp via degree-sorted perm: sub = lane>>3, lane l holds feats 4l..4l+3
__global__ void __launch_bounds__(256, 6)
k_l2(const float* __restrict__ b1, const float* __restrict__ W2) {
    __shared__ float4 sW[256];       // sW[k*8+l] = W2[k][4l..4l+3]
    __shared__ float4 sb[8];
    int t = threadIdx.x;
    const float4* W2v = (const float4*)W2;
    for (int i = t; i < 256; i += blockDim.x) sW[i] = W2v[i];
    if (t < 8) sb[t] = ((const float4*)b1)[t];
    __syncthreads();

    int gw   = (blockIdx.x * blockDim.x + t) >> 5;
    int lane = t & 31;
    int sub  = lane >> 3;
    int l    = lane & 7;
    int n    = g_perm[gw * 4 + sub];

    const uint2* h1 = (const uint2*)g_h1;            // [N][8] 8B units
    uint2 sv = h1[n * 8 + l];                        // self (pre-scaled)
    __half2 acc0 = *(__half2*)&sv.x;
    __half2 acc1 = *(__half2*)&sv.y;
    GATHER_ROW(h1, 8)

    float2 f0 = __half22float2(acc0);
    float2 f1 = __half22float2(acc1);
    float di = g_dinv[n];
    float4 bb = sb[l];
    float4 act;
    act.x = fmaxf(f0.x * di + bb.x, 0.0f);
    act.y = fmaxf(f0.y * di + bb.y, 0.0f);
    act.z = fmaxf(f1.x * di + bb.z, 0.0f);
    act.w = fmaxf(f1.y * di + bb.w, 0.0f);

    float4 hv = make_float4(0.f, 0.f, 0.f, 0.f);
    int bs = sub << 3;
    #pragma unroll
    for (int g = 0; g < 8; g++) {
        float v0 = __shfl_sync(0xFFFFFFFFu, act.x, bs + g);
        float v1 = __shfl_sync(0xFFFFFFFFu, act.y, bs + g);
        float v2 = __shfl_sync(0xFFFFFFFFu, act.z, bs + g);
        float v3 = __shfl_sync(0xFFFFFFFFu, act.w, bs + g);
        float4 w0 = sW[(4 * g + 0) * 8 + l];
        float4 w1 = sW[(4 * g + 1) * 8 + l];
        float4 w2 = sW[(4 * g + 2) * 8 + l];
        float4 w3 = sW[(4 * g + 3) * 8 + l];
        hv.x += v0 * w0.x + v1 * w1.x + v2 * w2.x + v3 * w3.x;
        hv.y += v0 * w0.y + v1 * w1.y + v2 * w2.y + v3 * w3.y;
        hv.z += v0 * w0.z + v1 * w1.z + v2 * w2.z + v3 * w3.z;
        hv.w += v0 * w0.w + v1 * w1.w + v2 * w2.w + v3 * w3.w;
    }
    uint2 o;
    *(__half2*)&o.x = __floats2half2_rn(hv.x * di, hv.y * di);
    *(__half2*)&o.y = __floats2half2_rn(hv.z * di, hv.w * di);
    ((uint2*)g_h2)[n * 8 + l] = o;
}

// ---------------- layer 3: gather(h2') + ReLU + GEMM(W3) -> h3' (fp16) ------
__global__ void __launch_bounds__(256, 6)
k_l3(const float* __restrict__ b2, const float* __restrict__ W3) {
    __shared__ float2 sW[256];       // sW[k*8+l] = W3[k][2l,2l+1]
    __shared__ float4 sb[8];
    int t = threadIdx.x;
    const float2* W3v = (const float2*)W3;
    for (int i = t; i < 256; i += blockDim.x) sW[i] = W3v[i];
    if (t < 8) sb[t] = ((const float4*)b2)[t];
    __syncthreads();

    int gw   = (blockIdx.x * blockDim.x + t) >> 5;
    int lane = t & 31;
    int sub  = lane >> 3;
    int l    = lane & 7;
    int n    = g_perm[gw * 4 + sub];

    const uint2* h2 = (const uint2*)g_h2;
    uint2 sv = h2[n * 8 + l];
    __half2 acc0 = *(__half2*)&sv.x;
    __half2 acc1 = *(__half2*)&sv.y;
    GATHER_ROW(h2, 8)

    float2 f0 = __half22float2(acc0);
    float2 f1 = __half22float2(acc1);
    float di = g_dinv[n];
    float4 bb = sb[l];
    float4 act;
    act.x = fmaxf(f0.x * di + bb.x, 0.0f);
    act.y = fmaxf(f0.y * di + bb.y, 0.0f);
    act.z = fmaxf(f1.x * di + bb.z, 0.0f);
    act.w = fmaxf(f1.y * di + bb.w, 0.0f);

    float2 hv = make_float2(0.f, 0.f);
    int bs = sub << 3;
    #pragma unroll
    for (int g = 0; g < 8; g++) {
        float v0 = __shfl_sync(0xFFFFFFFFu, act.x, bs + g);
        float v1 = __shfl_sync(0xFFFFFFFFu, act.y, bs + g);
        float v2 = __shfl_sync(0xFFFFFFFFu, act.z, bs + g);
        float v3 = __shfl_sync(0xFFFFFFFFu, act.w, bs + g);
        float2 w0 = sW[(4 * g + 0) * 8 + l];
        float2 w1 = sW[(4 * g + 1) * 8 + l];
        float2 w2 = sW[(4 * g + 2) * 8 + l];
        float2 w3 = sW[(4 * g + 3) * 8 + l];
        hv.x += v0 * w0.x + v1 * w1.x + v2 * w2.x + v3 * w3.x;
        hv.y += v0 * w0.y + v1 * w1.y + v2 * w2.y + v3 * w3.y;
    }
    ((__half2*)g_h3)[n * 8 + l] = __floats2half2_rn(hv.x * di, hv.y * di);
}

// ---------------- layer 4: gather(h3') + bias + log_softmax -> out ----------
// 8 nodes/warp via perm: sub = lane>>2, lane l in [0,4) holds classes 4l..4l+3
__global__ void __launch_bounds__(256, 6)
k_l4(const float* __restrict__ b3, float* __restrict__ out) {
    int t    = threadIdx.x;
    int gw   = (blockIdx.x * blockDim.x + t) >> 5;
    if (gw >= 12500) return;                         // warp-uniform exit
    int lane = t & 31;
    int sub  = lane >> 2;
    int l    = lane & 3;
    int n    = g_perm[gw * 8 + sub];

    const uint2* h3 = (const uint2*)g_h3;            // [N][4] 8B units
    uint2 sv = h3[n * 4 + l];
    __half2 acc0 = *(__half2*)&sv.x;
    __half2 acc1 = *(__half2*)&sv.y;
    GATHER_ROW(h3, 4)

    float2 f0 = __half22float2(acc0);
    float2 f1 = __half22float2(acc1);
    float di = g_dinv[n];
    float4 bb = ((const float4*)b3)[l];
    float4 vb;
    vb.x = f0.x * di + bb.x;
    vb.y = f0.y * di + bb.y;
    vb.z = f1.x * di + bb.z;
    vb.w = f1.y * di + bb.w;

    float m = fmaxf(fmaxf(vb.x, vb.y), fmaxf(vb.z, vb.w));
    m = fmaxf(m, __shfl_xor_sync(0xFFFFFFFFu, m, 2));
    m = fmaxf(m, __shfl_xor_sync(0xFFFFFFFFu, m, 1));
    float ss = expf(vb.x - m) + expf(vb.y - m) + expf(vb.z - m) + expf(vb.w - m);
    ss += __shfl_xor_sync(0xFFFFFFFFu, ss, 2);
    ss += __shfl_xor_sync(0xFFFFFFFFu, ss, 1);
    float lse = m + logf(ss);
    ((float4*)out)[n * 4 + l] =
        make_float4(vb.x - lse, vb.y - lse, vb.z - lse, vb.w - lse);
}

// ---------------- launch ----------------------------------------------------
extern "C" void kernel_launch(void* const* d_in, const int* in_sizes, int n_in,
                              void* d_out, int out_size) {
    // metadata order: x, edge_index, W1, b1, W2, b2, W3, b3
    const float* x  = (const float*)d_in[0];
    const int*   ei = (const int*)  d_in[1];   // [2, E]: src first, then dst
    const float* W1 = (const float*)d_in[2];
    const float* b1 = (const float*)d_in[3];
    const float* W2 = (const float*)d_in[4];
    const float* b2 = (const float*)d_in[5];
    const float* W3 = (const float*)d_in[6];
    const float* b3 = (const float*)d_in[7];
    float*       out = (float*)d_out;

    const int4* src4 = (const int4*)ei;
    const int4* dst4 = (const int4*)(ei + NEDGES);

    void *pcnt, *phist;
    cudaGetSymbolAddress(&pcnt, g_cnt);
    cudaGetSymbolAddress(&phist, g_hist);

    const int B = 256;
    cudaMemsetAsync(pcnt, 0, NNODES * sizeof(int));
    cudaMemsetAsync(phist, 0, NBIN * sizeof(int));
    k_build  <<<GE4 + GW, B>>>(src4, dst4, x, W1);
    k_prep   <<<GN, B>>>();
    k_binscan<<<1, 128>>>();
    k_place  <<<GN, B>>>();
    k_l2     <<<GQ, B>>>(b1, W2);
    k_l3     <<<GQ, B>>>(b2, W3);
    k_l4     <<<GO, B>>>(b3, out);
}

// round 12
// speedup vs baseline: 1.0785x; 1.0785x over previous
#include <cuda_runtime.h>
#include <cuda_fp16.h>
#include <math.h>

// Problem constants (fixed by the reference)
#define NNODES 100000
#define NEDGES 3200000
#define FIN    11
#define HDIM   32
#define CDIM   16
#define CAP    96      // padded CSR slots per node; deg ~ Poisson(32), P(>=96) ~ e^-41
#define CAP4   24      // CAP in int4 units

#define GE4 3125       // edge blocks, 4 edges/thread (3.2M / 4 / 256, exact)
#define GW  12500      // node-warp blocks for mm1 (100000 / 8, exact)
#define GO  1563       // 8-nodes-per-warp blocks (12500 warps, guarded)
#define GS  6250       // scale blocks: 100000*16 half2 / 256 (exact)

// ---------------- scratch (static __device__ — no allocation allowed) -------
__device__ int    g_cnt[NNODES];                       // in-degree / fill cursor
__device__ float  g_dinv[NNODES];
__device__ __align__(16) int    g_csr[NNODES * CAP];   // padded rows, src only
__device__ __align__(16) __half g_h1[NNODES * HDIM];   // after scale: h1 * dinv
__device__ __align__(16) __half g_h2[NNODES * HDIM];   // h2 * dinv
__device__ __align__(16) __half g_h3[NNODES * CDIM];   // h3 * dinv

// ---------------- fused: CSR fill (blocks [0,GE4)) ∥ mm1 (rest) -------------
__global__ void k_build(const int4* __restrict__ src4, const int4* __restrict__ dst4,
                        const float* __restrict__ x, const float* __restrict__ W1) {
    __shared__ float sW[FIN * HDIM];
    if (blockIdx.x < GE4) {
        int e = blockIdx.x * blockDim.x + threadIdx.x;
        int4 d = dst4[e];
        int4 s = src4[e];
        g_csr[d.x * CAP + atomicAdd(&g_cnt[d.x], 1)] = s.x;
        g_csr[d.y * CAP + atomicAdd(&g_cnt[d.y], 1)] = s.y;
        g_csr[d.z * CAP + atomicAdd(&g_cnt[d.z], 1)] = s.z;
        g_csr[d.w * CAP + atomicAdd(&g_cnt[d.w], 1)] = s.w;
    } else {
        int t = threadIdx.x;
        for (int i = t; i < FIN * HDIM; i += blockDim.x) sW[i] = W1[i];
        __syncthreads();
        int gw = ((blockIdx.x - GE4) * blockDim.x + t) >> 5;
        int l  = t & 31;
        float xv = (l < FIN) ? x[gw * FIN + l] : 0.0f;
        float acc = 0.0f;
        #pragma unroll
        for (int k = 0; k < FIN; k++)
            acc += __shfl_sync(0xFFFFFFFFu, xv, k) * sW[k * HDIM + l];
        g_h1[gw * HDIM + l] = __float2half(acc);
    }
}

// ---------------- dinv + in-place scale of h1 by dinv (coalesced, half2) ----
__global__ void k_scale() {
    int idx = blockIdx.x * blockDim.x + threadIdx.x;
    int n = idx >> 4;
    float di = rsqrtf((float)g_cnt[n] + 1.0f);
    if ((idx & 15) == 0) g_dinv[n] = di;
    __half2* h = (__half2*)g_h1;
    h[idx] = __hmul2(h[idx], __float2half2_rn(di));
}

// ---- gather over one padded CSR row into 4 half2 accs; 16B (uint4) lanes ---
// h = uint4 view of node rows (4 uint4 per 64B row); l in [0,4).
#define GATHER16(h)                                                           \
    const int4* row = (const int4*)&g_csr[n * CAP];                           \
    int deg = g_cnt[n];                                                       \
    int nIt = deg >> 2;                                                       \
    int4 q = row[0];                                                          \
    for (int j = 0; j < nIt; j++) {                                           \
        int4 qn = row[j + 1];            /* in-bounds: j+1 <= 23 < CAP4 */    \
        uint4 a = h[q.x * 4 + l];                                             \
        uint4 b = h[q.y * 4 + l];                                             \
        uint4 c = h[q.z * 4 + l];                                             \
        uint4 d = h[q.w * 4 + l];                                             \
        acc0 = __hadd2(acc0, __hadd2(__hadd2(*(__half2*)&a.x, *(__half2*)&b.x), \
                                     __hadd2(*(__half2*)&c.x, *(__half2*)&d.x))); \
        acc1 = __hadd2(acc1, __hadd2(__hadd2(*(__half2*)&a.y, *(__half2*)&b.y), \
                                     __hadd2(*(__half2*)&c.y, *(__half2*)&d.y))); \
        acc2 = __hadd2(acc2, __hadd2(__hadd2(*(__half2*)&a.z, *(__half2*)&b.z), \
                                     __hadd2(*(__half2*)&c.z, *(__half2*)&d.z))); \
        acc3 = __hadd2(acc3, __hadd2(__hadd2(*(__half2*)&a.w, *(__half2*)&b.w), \
                                     __hadd2(*(__half2*)&c.w, *(__half2*)&d.w))); \
        q = qn;                                                               \
    }                                                                         \
    int rem = deg & 3;                   /* q holds the final partial chunk */ \
    if (rem > 0) {                                                            \
        uint4 a = h[q.x * 4 + l];                                             \
        acc0 = __hadd2(acc0, *(__half2*)&a.x);                                \
        acc1 = __hadd2(acc1, *(__half2*)&a.y);                                \
        acc2 = __hadd2(acc2, *(__half2*)&a.z);                                \
        acc3 = __hadd2(acc3, *(__half2*)&a.w);                                \
    }                                                                         \
    if (rem > 1) {                                                            \
        uint4 a = h[q.y * 4 + l];                                             \
        acc0 = __hadd2(acc0, *(__half2*)&a.x);                                \
        acc1 = __hadd2(acc1, *(__half2*)&a.y);                                \
        acc2 = __hadd2(acc2, *(__half2*)&a.z);                                \
        acc3 = __hadd2(acc3, *(__half2*)&a.w);                                \
    }                                                                         \
    if (rem > 2) {                                                            \
        uint4 a = h[q.z * 4 + l];                                             \
        acc0 = __hadd2(acc0, *(__half2*)&a.x);                                \
        acc1 = __hadd2(acc1, *(__half2*)&a.y);                                \
        acc2 = __hadd2(acc2, *(__half2*)&a.z);                                \
        acc3 = __hadd2(acc3, *(__half2*)&a.w);                                \
    }

// ---------------- layer 2: gather(h1') + ReLU + GEMM(W2) -> h2' (fp16) ------
// 8 nodes/warp: sub = lane>>2, lane l in [0,4) holds feats {8l..8l+7}
__global__ void __launch_bounds__(256, 8)
k_l2(const float* __restrict__ b1, const float* __restrict__ W2) {
    __shared__ float4 sW[256];       // sW[k*8+m] = W2[k][4m..4m+3]
    __shared__ float  sb[HDIM];
    int t = threadIdx.x;
    const float4* W2v = (const float4*)W2;
    for (int i = t; i < 256; i += blockDim.x) sW[i] = W2v[i];
    if (t < HDIM) sb[t] = b1[t];
    __syncthreads();

    int gw = (blockIdx.x * blockDim.x + t) >> 5;
    if (gw >= GW) return;                            // warp-uniform exit
    int lane = t & 31;
    int sub  = lane >> 2;
    int l    = lane & 3;
    int n    = gw * 8 + sub;                         // consecutive -> coalesced

    const uint4* h1 = (const uint4*)g_h1;            // [N][4] 16B units
    uint4 sv = h1[n * 4 + l];                        // self (pre-scaled)
    __half2 acc0 = *(__half2*)&sv.x;
    __half2 acc1 = *(__half2*)&sv.y;
    __half2 acc2 = *(__half2*)&sv.z;
    __half2 acc3 = *(__half2*)&sv.w;
    GATHER16(h1)

    float di = g_dinv[n];
    float2 f0 = __half22float2(acc0);
    float2 f1 = __half22float2(acc1);
    float2 f2 = __half22float2(acc2);
    float2 f3 = __half22float2(acc3);
    float a0 = fmaxf(f0.x * di + sb[8 * l + 0], 0.0f);
    float a1 = fmaxf(f0.y * di + sb[8 * l + 1], 0.0f);
    float a2 = fmaxf(f1.x * di + sb[8 * l + 2], 0.0f);
    float a3 = fmaxf(f1.y * di + sb[8 * l + 3], 0.0f);
    float a4 = fmaxf(f2.x * di + sb[8 * l + 4], 0.0f);
    float a5 = fmaxf(f2.y * di + sb[8 * l + 5], 0.0f);
    float a6 = fmaxf(f3.x * di + sb[8 * l + 6], 0.0f);
    float a7 = fmaxf(f3.y * di + sb[8 * l + 7], 0.0f);

    float hv[8] = {0.f, 0.f, 0.f, 0.f, 0.f, 0.f, 0.f, 0.f};
    #pragma unroll
    for (int g = 0; g < 4; g++) {
        float av[8];
        av[0] = __shfl_sync(0xFFFFFFFFu, a0, g, 4);  // width-4: node's lane g
        av[1] = __shfl_sync(0xFFFFFFFFu, a1, g, 4);
        av[2] = __shfl_sync(0xFFFFFFFFu, a2, g, 4);
        av[3] = __shfl_sync(0xFFFFFFFFu, a3, g, 4);
        av[4] = __shfl_sync(0xFFFFFFFFu, a4, g, 4);
        av[5] = __shfl_sync(0xFFFFFFFFu, a5, g, 4);
        av[6] = __shfl_sync(0xFFFFFFFFu, a6, g, 4);
        av[7] = __shfl_sync(0xFFFFFFFFu, a7, g, 4);
        #pragma unroll
        for (int kk = 0; kk < 8; kk++) {
            int k = g * 8 + kk;
            float4 w0 = sW[k * 8 + 2 * l];
            float4 w1 = sW[k * 8 + 2 * l + 1];
            float v = av[kk];
            hv[0] += v * w0.x; hv[1] += v * w0.y;
            hv[2] += v * w0.z; hv[3] += v * w0.w;
            hv[4] += v * w1.x; hv[5] += v * w1.y;
            hv[6] += v * w1.z; hv[7] += v * w1.w;
        }
    }
    uint4 o;
    *(__half2*)&o.x = __floats2half2_rn(hv[0] * di, hv[1] * di);
    *(__half2*)&o.y = __floats2half2_rn(hv[2] * di, hv[3] * di);
    *(__half2*)&o.z = __floats2half2_rn(hv[4] * di, hv[5] * di);
    *(__half2*)&o.w = __floats2half2_rn(hv[6] * di, hv[7] * di);
    ((uint4*)g_h2)[n * 4 + l] = o;
}

// ---------------- layer 3: gather(h2') + ReLU + GEMM(W3) -> h3' (fp16) ------
// 8 nodes/warp; output C=16: lane l holds classes {4l..4l+3}
__global__ void __launch_bounds__(256, 8)
k_l3(const float* __restrict__ b2, const float* __restrict__ W3) {
    __shared__ float4 sW[128];       // sW[k*4+m] = W3[k][4m..4m+3]
    __shared__ float  sb[HDIM];
    int t = threadIdx.x;
    const float4* W3v = (const float4*)W3;
    for (int i = t; i < 128; i += blockDim.x) sW[i] = W3v[i];
    if (t < HDIM) sb[t] = b2[t];
    __syncthreads();

    int gw = (blockIdx.x * blockDim.x + t) >> 5;
    if (gw >= GW) return;
    int lane = t & 31;
    int sub  = lane >> 2;
    int l    = lane & 3;
    int n    = gw * 8 + sub;

    const uint4* h2 = (const uint4*)g_h2;
    uint4 sv = h2[n * 4 + l];
    __half2 acc0 = *(__half2*)&sv.x;
    __half2 acc1 = *(__half2*)&sv.y;
    __half2 acc2 = *(__half2*)&sv.z;
    __half2 acc3 = *(__half2*)&sv.w;
    GATHER16(h2)

    float di = g_dinv[n];
    float2 f0 = __half22float2(acc0);
    float2 f1 = __half22float2(acc1);
    float2 f2 = __half22float2(acc2);
    float2 f3 = __half22float2(acc3);
    float a0 = fmaxf(f0.x * di + sb[8 * l + 0], 0.0f);
    float a1 = fmaxf(f0.y * di + sb[8 * l + 1], 0.0f);
    float a2 = fmaxf(f1.x * di + sb[8 * l + 2], 0.0f);
    float a3 = fmaxf(f1.y * di + sb[8 * l + 3], 0.0f);
    float a4 = fmaxf(f2.x * di + sb[8 * l + 4], 0.0f);
    float a5 = fmaxf(f2.y * di + sb[8 * l + 5], 0.0f);
    float a6 = fmaxf(f3.x * di + sb[8 * l + 6], 0.0f);
    float a7 = fmaxf(f3.y * di + sb[8 * l + 7], 0.0f);

    float hv[4] = {0.f, 0.f, 0.f, 0.f};
    #pragma unroll
    for (int g = 0; g < 4; g++) {
        float av[8];
        av[0] = __shfl_sync(0xFFFFFFFFu, a0, g, 4);
        av[1] = __shfl_sync(0xFFFFFFFFu, a1, g, 4);
        av[2] = __shfl_sync(0xFFFFFFFFu, a2, g, 4);
        av[3] = __shfl_sync(0xFFFFFFFFu, a3, g, 4);
        av[4] = __shfl_sync(0xFFFFFFFFu, a4, g, 4);
        av[5] = __shfl_sync(0xFFFFFFFFu, a5, g, 4);
        av[6] = __shfl_sync(0xFFFFFFFFu, a6, g, 4);
        av[7] = __shfl_sync(0xFFFFFFFFu, a7, g, 4);
        #pragma unroll
        for (int kk = 0; kk < 8; kk++) {
            int k = g * 8 + kk;
            float4 w = sW[k * 4 + l];
            float v = av[kk];
            hv[0] += v * w.x; hv[1] += v * w.y;
            hv[2] += v * w.z; hv[3] += v * w.w;
        }
    }
    uint2 o;
    *(__half2*)&o.x = __floats2half2_rn(hv[0] * di, hv[1] * di);
    *(__half2*)&o.y = __floats2half2_rn(hv[2] * di, hv[3] * di);
    ((uint2*)g_h3)[n * 4 + l] = o;                   // node row = 32B = 4 uint2
}

// ---------------- layer 4: gather(h3') + bias + log_softmax -> out ----------
// 8 nodes/warp: sub = lane>>2, lane l in [0,4) holds classes {4l..4l+3}
__global__ void __launch_bounds__(256, 8)
k_l4(const float* __restrict__ b3, float* __restrict__ out) {
    int t    = threadIdx.x;
    int gw   = (blockIdx.x * blockDim.x + t) >> 5;
    if (gw >= GW) return;                            // warp-uniform exit
    int lane = t & 31;
    int sub  = lane >> 2;
    int l    = lane & 3;
    int n    = gw * 8 + sub;

    const uint2* h3 = (const uint2*)g_h3;            // [N][4] 8B units
    uint2 sv = h3[n * 4 + l];
    __half2 acc0 = *(__half2*)&sv.x;
    __half2 acc1 = *(__half2*)&sv.y;

    const int4* row = (const int4*)&g_csr[n * CAP];
    int deg = g_cnt[n];
    int nIt = deg >> 2;
    int4 q = row[0];
    for (int j = 0; j < nIt; j++) {
        int4 qn = row[j + 1];
        uint2 a = h3[q.x * 4 + l];
        uint2 b = h3[q.y * 4 + l];
        uint2 c = h3[q.z * 4 + l];
        uint2 d = h3[q.w * 4 + l];
        acc0 = __hadd2(acc0, __hadd2(__hadd2(*(__half2*)&a.x, *(__half2*)&b.x),
                                     __hadd2(*(__half2*)&c.x, *(__half2*)&d.x)));
        acc1 = __hadd2(acc1, __hadd2(__hadd2(*(__half2*)&a.y, *(__half2*)&b.y),
                                     __hadd2(*(__half2*)&c.y, *(__half2*)&d.y)));
        q = qn;
    }
    int rem = deg & 3;
    if (rem > 0) {
        uint2 a = h3[q.x * 4 + l];
        acc0 = __hadd2(acc0, *(__half2*)&a.x);
        acc1 = __hadd2(acc1, *(__half2*)&a.y);
    }
    if (rem > 1) {
        uint2 a = h3[q.y * 4 + l];
        acc0 = __hadd2(acc0, *(__half2*)&a.x);
        acc1 = __hadd2(acc1, *(__half2*)&a.y);
    }
    if (rem > 2) {
        uint2 a = h3[q.z * 4 + l];
        acc0 = __hadd2(acc0, *(__half2*)&a.x);
        acc1 = __hadd2(acc1, *(__half2*)&a.y);
    }

    float di = g_dinv[n];
    float2 f0 = __half22float2(acc0);
    float2 f1 = __half22float2(acc1);
    float4 bb = ((const float4*)b3)[l];
    float4 vb;
    vb.x = f0.x * di + bb.x;
    vb.y = f0.y * di + bb.y;
    vb.z = f1.x * di + bb.z;
    vb.w = f1.y * di + bb.w;

    float m = fmaxf(fmaxf(vb.x, vb.y), fmaxf(vb.z, vb.w));
    m = fmaxf(m, __shfl_xor_sync(0xFFFFFFFFu, m, 2));
    m = fmaxf(m, __shfl_xor_sync(0xFFFFFFFFu, m, 1));
    float ss = expf(vb.x - m) + expf(vb.y - m) + expf(vb.z - m) + expf(vb.w - m);
    ss += __shfl_xor_sync(0xFFFFFFFFu, ss, 2);
    ss += __shfl_xor_sync(0xFFFFFFFFu, ss, 1);
    float lse = m + logf(ss);
    ((float4*)out)[n * 4 + l] =
        make_float4(vb.x - lse, vb.y - lse, vb.z - lse, vb.w - lse);
}

// ---------------- launch ----------------------------------------------------
extern "C" void kernel_launch(void* const* d_in, const int* in_sizes, int n_in,
                              void* d_out, int out_size) {
    // metadata order: x, edge_index, W1, b1, W2, b2, W3, b3
    const float* x  = (const float*)d_in[0];
    const int*   ei = (const int*)  d_in[1];   // [2, E]: src first, then dst
    const float* W1 = (const float*)d_in[2];
    const float* b1 = (const float*)d_in[3];
    const float* W2 = (const float*)d_in[4];
    const float* b2 = (const float*)d_in[5];
    const float* W3 = (const float*)d_in[6];
    const float* b3 = (const float*)d_in[7];
    float*       out = (float*)d_out;

    const int4* src4 = (const int4*)ei;
    const int4* dst4 = (const int4*)(ei + NEDGES);

    void* pcnt;
    cudaGetSymbolAddress(&pcnt, g_cnt);

    const int B = 256;
    cudaMemsetAsync(pcnt, 0, NNODES * sizeof(int));
    k_build<<<GE4 + GW, B>>>(src4, dst4, x, W1);
    k_scale<<<GS, B>>>();
    k_l2   <<<GO, B>>>(b1, W2);
    k_l3   <<<GO, B>>>(b2, W3);
    k_l4   <<<GO, B>>>(b3, out);
}